// round 1
// baseline (speedup 1.0000x reference)
#include <cuda_runtime.h>
#include <math.h>

// Problem constants (fixed by the reference)
#define BB   2
#define NN   2000
#define KK   32
#define HH   128
#define NHD  4
#define DD   32
#define EPSC 1e-6f

// Packed weight scratch (__device__ globals: no allocation allowed).
// Layout: P[(jc*128 + i)*4 + u] = W[i][jc*4 + u]  -> LDG.128 coalesced across i.
__device__ float g_WQp [128 * 128];
__device__ float g_WK1p[128 * 128];
__device__ float g_WK2p[128 * 128];
__device__ float g_WVp [256 * 128];
__device__ float g_WOp [128 * 128];

__global__ void pack_kernel(const float* __restrict__ WQ,
                            const float* __restrict__ WK1,
                            const float* __restrict__ WK2,
                            const float* __restrict__ WV,
                            const float* __restrict__ WO) {
    int t = blockIdx.x * blockDim.x + threadIdx.x;
    if (t < 128 * 128) {
        int i = t >> 7, j = t & 127;
        int d = (((j >> 2) << 7) + i) * 4 + (j & 3);
        g_WQp [d] = WQ [t];
        g_WK1p[d] = WK1[t];
        g_WK2p[d] = WK2[t];
        g_WOp [d] = WO [t];
    }
    if (t < 256 * 128) {
        int i = t >> 8, j = t & 255;
        int d = (((j >> 2) << 7) + i) * 4 + (j & 3);
        g_WVp[d] = WV[t];
    }
}

// One block per node (bn in [0, B*N)), 128 threads.
// Thread t owns output feature i = t; warp w owns head h = w (d = 32 = warpsize).
__global__ void __launch_bounds__(128, 3)
spatppi_kernel(const float* __restrict__ h_V,
               const float* __restrict__ h_EV,
               const float* __restrict__ h_KV,
               const float* __restrict__ h_KE,
               const float* __restrict__ mask_V,
               const float* __restrict__ mask_attend,
               const float* __restrict__ gain,
               const float* __restrict__ bias,
               float* __restrict__ out) {
    extern __shared__ float sm[];
    float* s_xV     = sm;                 // 128
    float* s_ke     = s_xV + 128;         // 32*128 = 4096
    float* s_kv     = s_ke + 4096;        // 4096
    float* s_ev     = s_kv + 4096;        // 32*256 = 8192
    float* s_logits = s_ev + 8192;        // 4*32 = 128
    float* s_att    = s_logits + 128;     // 128
    float* s_y      = s_att + 128;        // 4*256 = 1024
    float* s_hu     = s_y + 1024;         // 128
    float* s_red    = s_hu + 128;         // 32

    const int bn   = blockIdx.x;
    const int t    = threadIdx.x;
    const int warp = t >> 5;
    const int lane = t & 31;

    // ---- stage node inputs into smem (fully coalesced float4) ----
    {
        if (t < 32)
            ((float4*)s_xV)[t] = ((const float4*)(h_V + (size_t)bn * 128))[t];
        const float4* gke = (const float4*)(h_KE + (size_t)bn * KK * 128);
        const float4* gkv = (const float4*)(h_KV + (size_t)bn * KK * 128);
        const float4* gev = (const float4*)(h_EV + (size_t)bn * KK * 256);
        float4* ske = (float4*)s_ke;
        float4* skv = (float4*)s_kv;
        float4* sev = (float4*)s_ev;
#pragma unroll
        for (int r = 0; r < 8; ++r)  ske[r * 128 + t] = gke[r * 128 + t];
#pragma unroll
        for (int r = 0; r < 8; ++r)  skv[r * 128 + t] = gkv[r * 128 + t];
#pragma unroll
        for (int r = 0; r < 16; ++r) sev[r * 128 + t] = gev[r * 128 + t];
    }
    __syncthreads();

    // ---- Q[i] = h_V . W_Q[i,:]  (thread i keeps its own q in a register) ----
    float q;
    {
        const float4* W = (const float4*)g_WQp;
        const float4* x = (const float4*)s_xV;
        float acc = 0.f;
#pragma unroll
        for (int jc = 0; jc < 32; ++jc) {
            float4 w = W[jc * 128 + t];
            float4 v = x[jc];
            acc += w.x * v.x + w.y * v.y + w.z * v.z + w.w * v.w;
        }
        q = acc;
    }

    // ---- phase 1: K1/K2 projections for all 32 neighbors, fused into logits ----
    // Register k-tile of 16 -> each packed weight LDG.128 is reused 16x.
    {
        const float4* W1 = (const float4*)g_WK1p;
        const float4* W2 = (const float4*)g_WK2p;
#pragma unroll
        for (int half = 0; half < 2; ++half) {
            float a1[16], a2[16];
#pragma unroll
            for (int kk = 0; kk < 16; ++kk) { a1[kk] = 0.f; a2[kk] = 0.f; }
            const float* ke0 = s_ke + (half * 16) * 128;
            const float* kv0 = s_kv + (half * 16) * 128;
            for (int jc = 0; jc < 32; ++jc) {
                float4 w1 = W1[jc * 128 + t];
                float4 w2 = W2[jc * 128 + t];
#pragma unroll
                for (int kk = 0; kk < 16; ++kk) {
                    float4 a = *(const float4*)(ke0 + kk * 128 + jc * 4);
                    float4 b = *(const float4*)(kv0 + kk * 128 + jc * 4);
                    a1[kk] += a.x * w1.x + a.y * w1.y + a.z * w1.z + a.w * w1.w;
                    a2[kk] += b.x * w2.x + b.y * w2.y + b.z * w2.z + b.w * w2.w;
                }
            }
            // logits[h][k] = (1/d) * sum_{d in head} q*K1*K2 : warp = head.
#pragma unroll
            for (int kk = 0; kk < 16; ++kk) {
                float p = q * a1[kk] * a2[kk];
#pragma unroll
                for (int off = 16; off > 0; off >>= 1)
                    p += __shfl_xor_sync(0xffffffffu, p, off);
                if (lane == 0)
                    s_logits[warp * 32 + half * 16 + kk] = p * (1.0f / 32.0f);
            }
        }
    }
    __syncthreads();

    // ---- masked softmax over neighbors (warp w = head w, lane = neighbor k) ----
    {
        float m = mask_attend[(size_t)bn * KK + lane];
        float l = s_logits[warp * 32 + lane];
        l = (m > 0.f) ? l : -3.402823466e38f;
        float mx = l;
#pragma unroll
        for (int off = 16; off > 0; off >>= 1)
            mx = fmaxf(mx, __shfl_xor_sync(0xffffffffu, mx, off));
        float e = expf(l - mx);   // masked lanes underflow to 0
        float s = e;
#pragma unroll
        for (int off = 16; off > 0; off >>= 1)
            s += __shfl_xor_sync(0xffffffffu, s, off);
        s_att[warp * 32 + lane] = m * e / s;
    }
    __syncthreads();

    // ---- y[h][j] = sum_k att[h][k] * h_EV[k][j]  (aggregate BEFORE W_V!) ----
#pragma unroll
    for (int r = 0; r < 8; ++r) {
        int idx = r * 128 + t;
        int h = idx >> 8;
        int j = idx & 255;
        float acc = 0.f;
#pragma unroll
        for (int k = 0; k < 32; ++k)
            acc += s_att[h * 32 + k] * s_ev[k * 256 + j];
        s_y[idx] = acc;
    }
    __syncthreads();

    // ---- h_up[i] = y[head(i)] . W_V[i,:]  ----
    {
        int h = t >> 5;
        const float4* W  = (const float4*)g_WVp;
        const float4* yv = (const float4*)(s_y + h * 256);
        float acc = 0.f;
#pragma unroll 4
        for (int jc = 0; jc < 64; ++jc) {
            float4 w = W[jc * 128 + t];
            float4 v = yv[jc];
            acc += w.x * v.x + w.y * v.y + w.z * v.z + w.w * v.w;
        }
        s_hu[t] = acc;
    }
    __syncthreads();

    // ---- dh[i] = h_up . W_O[i,:]; residual ----
    float x;
    {
        const float4* W = (const float4*)g_WOp;
        const float4* u = (const float4*)s_hu;
        float acc = 0.f;
#pragma unroll 8
        for (int jc = 0; jc < 32; ++jc) {
            float4 w = W[jc * 128 + t];
            float4 v = u[jc];
            acc += w.x * v.x + w.y * v.y + w.z * v.z + w.w * v.w;
        }
        x = s_xV[t] + acc;
    }

    // ---- LayerNorm (unbiased var, two-pass), gain/bias, node mask ----
    float v = x;
#pragma unroll
    for (int off = 16; off > 0; off >>= 1)
        v += __shfl_xor_sync(0xffffffffu, v, off);
    if (lane == 0) s_red[warp] = v;
    __syncthreads();
    float mu = (s_red[0] + s_red[1] + s_red[2] + s_red[3]) * (1.f / 128.f);
    __syncthreads();
    float dv = (x - mu) * (x - mu);
#pragma unroll
    for (int off = 16; off > 0; off >>= 1)
        dv += __shfl_xor_sync(0xffffffffu, dv, off);
    if (lane == 0) s_red[warp] = dv;
    __syncthreads();
    float var   = (s_red[0] + s_red[1] + s_red[2] + s_red[3]) * (1.f / 127.f);
    float sigma = sqrtf(var + EPSC);
    float o = gain[t] * (x - mu) / (sigma + EPSC) + bias[t];
    out[(size_t)bn * 128 + t] = mask_V[bn] * o;
}

static const int SMEM_FLOATS = 128 + 4096 + 4096 + 8192 + 128 + 128 + 1024 + 128 + 32;

extern "C" void kernel_launch(void* const* d_in, const int* in_sizes, int n_in,
                              void* d_out, int out_size) {
    const float* h_V         = (const float*)d_in[0];
    const float* h_EV        = (const float*)d_in[1];
    const float* h_KV        = (const float*)d_in[2];
    const float* h_KE        = (const float*)d_in[3];
    const float* mask_V      = (const float*)d_in[4];
    const float* mask_attend = (const float*)d_in[5];
    const float* W_Q         = (const float*)d_in[6];
    const float* W_K1        = (const float*)d_in[7];
    const float* W_K2        = (const float*)d_in[8];
    const float* W_V         = (const float*)d_in[9];
    const float* W_O         = (const float*)d_in[10];
    const float* gain        = (const float*)d_in[11];
    const float* bias        = (const float*)d_in[12];
    float* out = (float*)d_out;

    // Pack weights into coalesced [jc][i][4] layout (runs every launch; tiny).
    pack_kernel<<<128, 256>>>(W_Q, W_K1, W_K2, W_V, W_O);

    const int smem_bytes = SMEM_FLOATS * (int)sizeof(float);
    cudaFuncSetAttribute(spatppi_kernel,
                         cudaFuncAttributeMaxDynamicSharedMemorySize, smem_bytes);
    spatppi_kernel<<<BB * NN, 128, smem_bytes>>>(
        h_V, h_EV, h_KV, h_KE, mask_V, mask_attend, gain, bias, out);
}

// round 3
// speedup vs baseline: 3.2567x; 3.2567x over previous
#include <cuda_runtime.h>
#include <cuda_fp16.h>
#include <cstdint>
#include <math.h>

#define BB   2
#define NN   2000
#define KK   32
#define HH   128
#define EPSC 1e-6f

// ---------------- packed weight scratch (__device__ globals) ----------------
// fp32 packs (coalesced [jc][i][4]) for Q, V, O paths:
__device__ float g_WQp [128 * 128];
__device__ float g_WVp [256 * 128];
__device__ float g_WOp [128 * 128];
// fp16 B-fragment packs for K1/K2 mma: index f = ((nt8*8 + ks)*32 + lane),
// uint2 = {half2(B[k0],B[k0+1]), half2(B[k0+8],B[k0+9])}, B[k][n] = W[n][k].
__device__ uint2 g_W1f[16 * 8 * 32];
__device__ uint2 g_W2f[16 * 8 * 32];

__global__ void pack_kernel(const float* __restrict__ WQ,
                            const float* __restrict__ WK1,
                            const float* __restrict__ WK2,
                            const float* __restrict__ WV,
                            const float* __restrict__ WO) {
    int t = blockIdx.x * blockDim.x + threadIdx.x;
    if (t < 128 * 128) {
        int i = t >> 7, j = t & 127;
        int d = (((j >> 2) << 7) + i) * 4 + (j & 3);
        g_WQp[d] = WQ[t];
        g_WOp[d] = WO[t];
    }
    if (t < 256 * 128) {
        int i = t >> 8, j = t & 255;
        int d = (((j >> 2) << 7) + i) * 4 + (j & 3);
        g_WVp[d] = WV[t];
    }
    if (t < 16 * 8 * 32) {
        int lane = t & 31;
        int ks   = (t >> 5) & 7;
        int nt8  = t >> 8;               // which 8-wide N tile (0..15)
        int g    = lane >> 2;
        int tid4 = lane & 3;
        int n    = nt8 * 8 + g;
        int k0   = ks * 16 + tid4 * 2;
        __half2 x1 = __floats2half2_rn(WK1[n * 128 + k0],     WK1[n * 128 + k0 + 1]);
        __half2 y1 = __floats2half2_rn(WK1[n * 128 + k0 + 8], WK1[n * 128 + k0 + 9]);
        __half2 x2 = __floats2half2_rn(WK2[n * 128 + k0],     WK2[n * 128 + k0 + 1]);
        __half2 y2 = __floats2half2_rn(WK2[n * 128 + k0 + 8], WK2[n * 128 + k0 + 9]);
        uint2 u1, u2;
        u1.x = *(unsigned int*)&x1; u1.y = *(unsigned int*)&y1;
        u2.x = *(unsigned int*)&x2; u2.y = *(unsigned int*)&y2;
        g_W1f[t] = u1;
        g_W2f[t] = u2;
    }
}

// ---------------- PTX helpers ----------------
__device__ __forceinline__ void ldsm_x4(unsigned int* r, const void* p) {
    unsigned int a = (unsigned int)__cvta_generic_to_shared(p);
    asm volatile("ldmatrix.sync.aligned.m8n8.x4.shared.b16 {%0,%1,%2,%3}, [%4];"
                 : "=r"(r[0]), "=r"(r[1]), "=r"(r[2]), "=r"(r[3]) : "r"(a));
}
__device__ __forceinline__ void mma16816(float* d, const unsigned int* a,
                                         unsigned int b0, unsigned int b1) {
    asm volatile("mma.sync.aligned.m16n8k16.row.col.f32.f16.f16.f32 "
                 "{%0,%1,%2,%3}, {%4,%5,%6,%7}, {%8,%9}, {%0,%1,%2,%3};"
                 : "+f"(d[0]), "+f"(d[1]), "+f"(d[2]), "+f"(d[3])
                 : "r"(a[0]), "r"(a[1]), "r"(a[2]), "r"(a[3]), "r"(b0), "r"(b1));
}

// padded half-tile row stride (32 rows x 128 cols, +8 halves pad)
#define KROW 136

// One block per node, 128 threads. Warp w = head w (features 32w..32w+31).
__global__ void __launch_bounds__(128, 3)
spatppi_kernel(const float* __restrict__ h_V,
               const float* __restrict__ h_EV,
               const float* __restrict__ h_KV,
               const float* __restrict__ h_KE,
               const float* __restrict__ mask_V,
               const float* __restrict__ mask_attend,
               const float* __restrict__ gain,
               const float* __restrict__ bias,
               float* __restrict__ out) {
    extern __shared__ float smbuf[];
    float* s_xV     = smbuf;              // 128
    float* s_q      = s_xV + 128;         // 128
    float* s_ev     = s_q + 128;          // 8192
    float* s_logits = s_ev + 8192;        // 128
    float* s_att    = s_logits + 128;     // 128
    float* s_y      = s_att + 128;        // 1024
    float* s_hu     = s_y + 1024;         // 128
    float* s_red    = s_hu + 128;         // 32
    __half* s_keh   = (__half*)(s_red + 32);     // 32*KROW halves
    __half* s_kvh   = s_keh + 32 * KROW;         // 32*KROW halves

    const int bn   = blockIdx.x;
    const int t    = threadIdx.x;
    const int w    = t >> 5;
    const int lane = t & 31;
    const int g    = lane >> 2;
    const int tid4 = lane & 3;

    // ---------------- stage inputs ----------------
    {
        if (t < 32)
            ((float4*)s_xV)[t] = ((const float4*)(h_V + (size_t)bn * 128))[t];
        const float4* gke = (const float4*)(h_KE + (size_t)bn * KK * 128);
        const float4* gkv = (const float4*)(h_KV + (size_t)bn * KK * 128);
        const float4* gev = (const float4*)(h_EV + (size_t)bn * KK * 256);
        float4* sev = (float4*)s_ev;
#pragma unroll
        for (int r = 0; r < 8; ++r) {
            int e4 = r * 128 + t;            // float4 index over 32x128
            int k  = e4 >> 5;
            int j  = (e4 & 31) * 4;
            float4 a = gke[e4];
            float4 b = gkv[e4];
            __half2* pk = (__half2*)(s_keh + k * KROW + j);
            __half2* pv = (__half2*)(s_kvh + k * KROW + j);
            pk[0] = __floats2half2_rn(a.x, a.y);
            pk[1] = __floats2half2_rn(a.z, a.w);
            pv[0] = __floats2half2_rn(b.x, b.y);
            pv[1] = __floats2half2_rn(b.z, b.w);
        }
#pragma unroll
        for (int r = 0; r < 16; ++r) sev[r * 128 + t] = gev[r * 128 + t];
    }
    __syncthreads();

    // ---------------- Q[i] = h_V . W_Q[i,:] (fp32) ----------------
    {
        const float4* Wp = (const float4*)g_WQp;
        const float4* xp = (const float4*)s_xV;
        float acc = 0.f;
#pragma unroll
        for (int jc = 0; jc < 32; ++jc) {
            float4 wv = Wp[jc * 128 + t];
            float4 v  = xp[jc];
            acc += wv.x * v.x + wv.y * v.y + wv.z * v.z + wv.w * v.w;
        }
        s_q[t] = acc;
    }
    __syncwarp();

    // ---------------- K1/K2 via tensor-core mma (fp16 in, fp32 acc) --------
    // acc[m][nt][4]: C rows m*16+{g,g+8} (=neighbor k), cols w*32+nt*8+tid4*2+{0,1}
    float acc1[2][4][4], acc2[2][4][4];
#pragma unroll
    for (int m = 0; m < 2; ++m)
#pragma unroll
        for (int nt = 0; nt < 4; ++nt)
#pragma unroll
            for (int c = 0; c < 4; ++c) { acc1[m][nt][c] = 0.f; acc2[m][nt][c] = 0.f; }

    const int arow  = lane & 15;
    const int acol8 = (lane >> 4) * 8;
#pragma unroll
    for (int ks = 0; ks < 8; ++ks) {
        unsigned int a1[2][4], a2[2][4];
#pragma unroll
        for (int m = 0; m < 2; ++m) {
            const __half* pa = s_keh + (m * 16 + arow) * KROW + ks * 16 + acol8;
            const __half* pb = s_kvh + (m * 16 + arow) * KROW + ks * 16 + acol8;
            ldsm_x4(a1[m], pa);
            ldsm_x4(a2[m], pb);
        }
#pragma unroll
        for (int nt = 0; nt < 4; ++nt) {
            int f = (((w * 4 + nt) * 8 + ks) * 32) + lane;
            uint2 b1 = g_W1f[f];
            uint2 b2 = g_W2f[f];
            mma16816(acc1[0][nt], a1[0], b1.x, b1.y);
            mma16816(acc1[1][nt], a1[1], b1.x, b1.y);
            mma16816(acc2[0][nt], a2[0], b2.x, b2.y);
            mma16816(acc2[1][nt], a2[1], b2.x, b2.y);
        }
    }

    // ---------------- logits[h=w][k] = (1/32) sum_i q*K1*K2 ----------------
#pragma unroll
    for (int m = 0; m < 2; ++m) {
        float p0 = 0.f, p1 = 0.f;
#pragma unroll
        for (int nt = 0; nt < 4; ++nt) {
            int j0 = w * 32 + nt * 8 + tid4 * 2;
            float q0 = s_q[j0], q1 = s_q[j0 + 1];
            p0 += q0 * acc1[m][nt][0] * acc2[m][nt][0]
                + q1 * acc1[m][nt][1] * acc2[m][nt][1];
            p1 += q0 * acc1[m][nt][2] * acc2[m][nt][2]
                + q1 * acc1[m][nt][3] * acc2[m][nt][3];
        }
        p0 += __shfl_xor_sync(0xffffffffu, p0, 1);
        p0 += __shfl_xor_sync(0xffffffffu, p0, 2);
        p1 += __shfl_xor_sync(0xffffffffu, p1, 1);
        p1 += __shfl_xor_sync(0xffffffffu, p1, 2);
        if (tid4 == 0) {
            s_logits[w * 32 + m * 16 + g]     = p0 * (1.0f / 32.0f);
            s_logits[w * 32 + m * 16 + g + 8] = p1 * (1.0f / 32.0f);
        }
    }
    __syncwarp();

    // ---------------- masked softmax (warp w = head, lane = neighbor) ------
    {
        float mk = mask_attend[(size_t)bn * KK + lane];
        float l  = s_logits[w * 32 + lane];
        l = (mk > 0.f) ? l : -3.402823466e38f;
        float mx = l;
#pragma unroll
        for (int off = 16; off > 0; off >>= 1)
            mx = fmaxf(mx, __shfl_xor_sync(0xffffffffu, mx, off));
        float e = expf(l - mx);
        float s = e;
#pragma unroll
        for (int off = 16; off > 0; off >>= 1)
            s += __shfl_xor_sync(0xffffffffu, s, off);
        s_att[w * 32 + lane] = mk * e / s;
    }
    __syncthreads();

    // ---------------- y[h][j] = sum_k att[h][k] * h_EV[k][j] (fp32) --------
#pragma unroll
    for (int r = 0; r < 8; ++r) {
        int idx = r * 128 + t;
        int h = idx >> 8;
        int j = idx & 255;
        float a = 0.f;
#pragma unroll
        for (int k = 0; k < 32; ++k)
            a += s_att[h * 32 + k] * s_ev[k * 256 + j];
        s_y[idx] = a;
    }
    __syncthreads();

    // ---------------- h_up[i] = y[head(i)] . W_V[i,:] ----------------------
    {
        int h = t >> 5;
        const float4* Wp = (const float4*)g_WVp;
        const float4* yv = (const float4*)(s_y + h * 256);
        float a = 0.f;
#pragma unroll 4
        for (int jc = 0; jc < 64; ++jc) {
            float4 wv = Wp[jc * 128 + t];
            float4 v  = yv[jc];
            a += wv.x * v.x + wv.y * v.y + wv.z * v.z + wv.w * v.w;
        }
        s_hu[t] = a;
    }
    __syncthreads();

    // ---------------- dh = h_up . W_O[i,:]; residual ------------------------
    float x;
    {
        const float4* Wp = (const float4*)g_WOp;
        const float4* up = (const float4*)s_hu;
        float a = 0.f;
#pragma unroll 8
        for (int jc = 0; jc < 32; ++jc) {
            float4 wv = Wp[jc * 128 + t];
            float4 v  = up[jc];
            a += wv.x * v.x + wv.y * v.y + wv.z * v.z + wv.w * v.w;
        }
        x = s_xV[t] + a;
    }

    // ---------------- LayerNorm (unbiased), gain/bias, node mask -----------
    float v = x;
#pragma unroll
    for (int off = 16; off > 0; off >>= 1)
        v += __shfl_xor_sync(0xffffffffu, v, off);
    if (lane == 0) s_red[w] = v;
    __syncthreads();
    float mu = (s_red[0] + s_red[1] + s_red[2] + s_red[3]) * (1.f / 128.f);
    __syncthreads();
    float dv = (x - mu) * (x - mu);
#pragma unroll
    for (int off = 16; off > 0; off >>= 1)
        dv += __shfl_xor_sync(0xffffffffu, dv, off);
    if (lane == 0) s_red[w] = dv;
    __syncthreads();
    float var   = (s_red[0] + s_red[1] + s_red[2] + s_red[3]) * (1.f / 127.f);
    float sigma = sqrtf(var + EPSC);
    float o = gain[t] * (x - mu) / (sigma + EPSC) + bias[t];
    out[(size_t)bn * 128 + t] = mask_V[bn] * o;
}

static const int SMEM_BYTES =
    (128 + 128 + 8192 + 128 + 128 + 1024 + 128 + 32) * 4  // fp32 sections
    + 2 * 32 * KROW * 2;                                   // half tiles

extern "C" void kernel_launch(void* const* d_in, const int* in_sizes, int n_in,
                              void* d_out, int out_size) {
    const float* h_V         = (const float*)d_in[0];
    const float* h_EV        = (const float*)d_in[1];
    const float* h_KV        = (const float*)d_in[2];
    const float* h_KE        = (const float*)d_in[3];
    const float* mask_V      = (const float*)d_in[4];
    const float* mask_attend = (const float*)d_in[5];
    const float* W_Q         = (const float*)d_in[6];
    const float* W_K1        = (const float*)d_in[7];
    const float* W_K2        = (const float*)d_in[8];
    const float* W_V         = (const float*)d_in[9];
    const float* W_O         = (const float*)d_in[10];
    const float* gain        = (const float*)d_in[11];
    const float* bias        = (const float*)d_in[12];
    float* out = (float*)d_out;

    pack_kernel<<<128, 256>>>(W_Q, W_K1, W_K2, W_V, W_O);

    cudaFuncSetAttribute(spatppi_kernel,
                         cudaFuncAttributeMaxDynamicSharedMemorySize, SMEM_BYTES);
    spatppi_kernel<<<BB * NN, 128, SMEM_BYTES>>>(
        h_V, h_EV, h_KV, h_KE, mask_V, mask_attend, gain, bias, out);
}

// round 4
// speedup vs baseline: 3.6658x; 1.1256x over previous
#include <cuda_runtime.h>
#include <cuda_fp16.h>
#include <cstdint>
#include <math.h>

#define BB   2
#define NN   2000
#define KK   32
#define HH   128
#define EPSC 1e-6f

// ---------------- device scratch (__device__ globals, no alloc) -------------
// mma B-fragment packs: index ((nt*KS + ks)*32 + lane),
// uint2 = {half2(B[k0],B[k0+1]), half2(B[k0+8],B[k0+9])}, B[k][n] = W[n][k].
__device__ uint2 g_WQf[16 * 8 * 32];
__device__ uint2 g_W1f[16 * 8 * 32];
__device__ uint2 g_W2f[16 * 8 * 32];
// Fused value matrix Mfull[1024 x 128] fp16 fragments: Mfull[h*256+j][o] =
// sum_{ii} W_O[o, h*32+ii] * W_V[h*32+ii, j].   index ((nt*64 + ks)*32 + lane)
__device__ uint2 g_Mf[16 * 64 * 32];
// Q fp16 [4000 x 128], Y fp16 [4000 x 1024]
__device__ __half g_Qh[4000 * 128];
__device__ __half g_Y [4000 * 1024];

__device__ __forceinline__ unsigned int h2u(__half2 h) {
    return *(unsigned int*)&h;
}

// ---------------- pack: weight fragments + Mfull ----------------------------
// blocks [0,16): W_Q/W_K1/W_K2 fragment packs. blocks [16,48): Mfull.
__global__ void pack_kernel(const float* __restrict__ WQ,
                            const float* __restrict__ WK1,
                            const float* __restrict__ WK2,
                            const float* __restrict__ WV,
                            const float* __restrict__ WO) {
    __shared__ float sWO[128 * 33];
    __shared__ float sWV[32 * 32];
    if (blockIdx.x < 16) {
        int t = blockIdx.x * 256 + threadIdx.x;   // 0..4095
        int lane = t & 31;
        int ks   = (t >> 5) & 7;
        int nt8  = t >> 8;
        int g    = lane >> 2;
        int tid4 = lane & 3;
        int n    = nt8 * 8 + g;
        int k0   = ks * 16 + tid4 * 2;
        uint2 uq, u1, u2;
        uq.x = h2u(__floats2half2_rn(WQ [n * 128 + k0],     WQ [n * 128 + k0 + 1]));
        uq.y = h2u(__floats2half2_rn(WQ [n * 128 + k0 + 8], WQ [n * 128 + k0 + 9]));
        u1.x = h2u(__floats2half2_rn(WK1[n * 128 + k0],     WK1[n * 128 + k0 + 1]));
        u1.y = h2u(__floats2half2_rn(WK1[n * 128 + k0 + 8], WK1[n * 128 + k0 + 9]));
        u2.x = h2u(__floats2half2_rn(WK2[n * 128 + k0],     WK2[n * 128 + k0 + 1]));
        u2.y = h2u(__floats2half2_rn(WK2[n * 128 + k0 + 8], WK2[n * 128 + k0 + 9]));
        g_WQf[t] = uq; g_W1f[t] = u1; g_W2f[t] = u2;
    } else {
        int bid = blockIdx.x - 16;        // 0..31
        int h   = bid >> 3;               // head
        int jc  = bid & 7;                // 32-wide j chunk within head
        int tid = threadIdx.x;
        for (int i = tid; i < 128 * 32; i += 256) {
            int o = i >> 5, ii = i & 31;
            sWO[o * 33 + ii] = WO[o * 128 + h * 32 + ii];
        }
        for (int i = tid; i < 32 * 32; i += 256) {
            int ii = i >> 5, jj = i & 31;
            sWV[ii * 32 + jj] = WV[(h * 32 + ii) * 256 + jc * 32 + jj];
        }
        __syncthreads();
        int o    = tid & 127;
        int jsel = tid >> 7;              // which 16-wide half of the 32 jj's
        float wo[32];
#pragma unroll
        for (int ii = 0; ii < 32; ++ii) wo[ii] = sWO[o * 33 + ii];
        float m[16];
#pragma unroll
        for (int jj2 = 0; jj2 < 16; ++jj2) {
            int jj = jsel * 16 + jj2;
            float a = 0.f;
#pragma unroll
            for (int ii = 0; ii < 32; ++ii) a += sWV[ii * 32 + jj] * wo[ii];
            m[jj2] = a;
        }
        int ks = h * 16 + jc * 2 + jsel;
        int nt = o >> 3;
        int g  = o & 7;
#pragma unroll
        for (int tid4 = 0; tid4 < 4; ++tid4) {
            int k0l = tid4 * 2;
            uint2 u;
            u.x = h2u(__floats2half2_rn(m[k0l],     m[k0l + 1]));
            u.y = h2u(__floats2half2_rn(m[k0l + 8], m[k0l + 9]));
            g_Mf[(nt * 64 + ks) * 32 + (g << 2 | tid4)] = u;
        }
    }
}

// ---------------- PTX helpers ----------------
__device__ __forceinline__ void ldsm_x4(unsigned int* r, const void* p) {
    unsigned int a = (unsigned int)__cvta_generic_to_shared(p);
    asm volatile("ldmatrix.sync.aligned.m8n8.x4.shared.b16 {%0,%1,%2,%3}, [%4];"
                 : "=r"(r[0]), "=r"(r[1]), "=r"(r[2]), "=r"(r[3]) : "r"(a));
}
__device__ __forceinline__ void mma16816(float* d, const unsigned int* a,
                                         unsigned int b0, unsigned int b1) {
    asm volatile("mma.sync.aligned.m16n8k16.row.col.f32.f16.f16.f32 "
                 "{%0,%1,%2,%3}, {%4,%5,%6,%7}, {%8,%9}, {%0,%1,%2,%3};"
                 : "+f"(d[0]), "+f"(d[1]), "+f"(d[2]), "+f"(d[3])
                 : "r"(a[0]), "r"(a[1]), "r"(a[2]), "r"(a[3]), "r"(b0), "r"(b1));
}

// ---------------- qgemm: Q = h_V @ W_Q^T -> g_Qh (fp16 mma) -----------------
// 125 blocks x 128 threads, 32 nodes/block.
__global__ void __launch_bounds__(128)
qgemm_kernel(const float* __restrict__ h_V) {
    __shared__ __half sA[32 * 136];
    const int t    = threadIdx.x;
    const int w    = t >> 5;
    const int lane = t & 31;
    const int g    = lane >> 2;
    const int tid4 = lane & 3;
    const int node0 = blockIdx.x * 32;

    const float4* hv4 = (const float4*)h_V;
#pragma unroll
    for (int it = 0; it < 8; ++it) {
        int f4 = it * 128 + t;            // 0..1023
        int r  = f4 >> 5, c4 = f4 & 31;
        float4 v = hv4[(size_t)(node0 + r) * 32 + c4];
        __half2* p = (__half2*)(sA + r * 136 + c4 * 4);
        p[0] = __floats2half2_rn(v.x, v.y);
        p[1] = __floats2half2_rn(v.z, v.w);
    }
    __syncthreads();

    float acc[2][4][4];
#pragma unroll
    for (int m = 0; m < 2; ++m)
#pragma unroll
        for (int n = 0; n < 4; ++n)
#pragma unroll
            for (int c = 0; c < 4; ++c) acc[m][n][c] = 0.f;

    const int arow = lane & 15, acol8 = (lane >> 4) * 8;
#pragma unroll
    for (int ks = 0; ks < 8; ++ks) {
        unsigned int a[2][4];
#pragma unroll
        for (int m = 0; m < 2; ++m)
            ldsm_x4(a[m], sA + (m * 16 + arow) * 136 + ks * 16 + acol8);
#pragma unroll
        for (int n = 0; n < 4; ++n) {
            uint2 b = g_WQf[(((w * 4 + n) * 8 + ks) * 32) + lane];
            mma16816(acc[0][n], a[0], b.x, b.y);
            mma16816(acc[1][n], a[1], b.x, b.y);
        }
    }
#pragma unroll
    for (int m = 0; m < 2; ++m)
#pragma unroll
        for (int n = 0; n < 4; ++n) {
            int col = w * 32 + n * 8 + tid4 * 2;
            int r0  = node0 + m * 16 + g;
            *(__half2*)&g_Qh[(size_t)r0 * 128 + col] =
                __floats2half2_rn(acc[m][n][0], acc[m][n][1]);
            *(__half2*)&g_Qh[(size_t)(r0 + 8) * 128 + col] =
                __floats2half2_rn(acc[m][n][2], acc[m][n][3]);
        }
}

// ---------------- kernel1: attention per node -> Y --------------------------
#define KROW 136
__global__ void __launch_bounds__(128, 4)
attn_kernel(const float* __restrict__ h_EV,
            const float* __restrict__ h_KV,
            const float* __restrict__ h_KE,
            const float* __restrict__ mask_attend) {
    extern __shared__ float smbuf[];
    float*  s_q      = smbuf;                    // 128
    float*  s_logits = s_q + 128;                // 128
    __half* s_keh    = (__half*)(s_logits + 128);
    __half* s_kvh    = s_keh + 32 * KROW;

    const int bn   = blockIdx.x;
    const int t    = threadIdx.x;
    const int w    = t >> 5;
    const int lane = t & 31;
    const int g    = lane >> 2;
    const int tid4 = lane & 3;

    // stage KE/KV as fp16 (coalesced float4 LDG)
    {
        const float4* gke = (const float4*)(h_KE + (size_t)bn * KK * 128);
        const float4* gkv = (const float4*)(h_KV + (size_t)bn * KK * 128);
#pragma unroll
        for (int r = 0; r < 8; ++r) {
            int e4 = r * 128 + t;
            int k  = e4 >> 5;
            int j  = (e4 & 31) * 4;
            float4 a = gke[e4];
            float4 b = gkv[e4];
            uint2 ua, ub;
            ua.x = h2u(__floats2half2_rn(a.x, a.y));
            ua.y = h2u(__floats2half2_rn(a.z, a.w));
            ub.x = h2u(__floats2half2_rn(b.x, b.y));
            ub.y = h2u(__floats2half2_rn(b.z, b.w));
            *(uint2*)(s_keh + k * KROW + j) = ua;
            *(uint2*)(s_kvh + k * KROW + j) = ub;
        }
        s_q[t] = __half2float(g_Qh[(size_t)bn * 128 + t]);
    }
    __syncthreads();

    // K1/K2 mma (fp16 in, fp32 acc). rows = neighbors, cols = features.
    float acc1[2][4][4], acc2[2][4][4];
#pragma unroll
    for (int m = 0; m < 2; ++m)
#pragma unroll
        for (int n = 0; n < 4; ++n)
#pragma unroll
            for (int c = 0; c < 4; ++c) { acc1[m][n][c] = 0.f; acc2[m][n][c] = 0.f; }

    const int arow = lane & 15, acol8 = (lane >> 4) * 8;
#pragma unroll
    for (int ks = 0; ks < 8; ++ks) {
        unsigned int a1[2][4], a2[2][4];
#pragma unroll
        for (int m = 0; m < 2; ++m) {
            ldsm_x4(a1[m], s_keh + (m * 16 + arow) * KROW + ks * 16 + acol8);
            ldsm_x4(a2[m], s_kvh + (m * 16 + arow) * KROW + ks * 16 + acol8);
        }
#pragma unroll
        for (int n = 0; n < 4; ++n) {
            int f = (((w * 4 + n) * 8 + ks) * 32) + lane;
            uint2 b1 = g_W1f[f];
            uint2 b2 = g_W2f[f];
            mma16816(acc1[0][n], a1[0], b1.x, b1.y);
            mma16816(acc1[1][n], a1[1], b1.x, b1.y);
            mma16816(acc2[0][n], a2[0], b2.x, b2.y);
            mma16816(acc2[1][n], a2[1], b2.x, b2.y);
        }
    }

    // logits[h=w][k] = (1/32) sum_i q*K1*K2
#pragma unroll
    for (int m = 0; m < 2; ++m) {
        float p0 = 0.f, p1 = 0.f;
#pragma unroll
        for (int n = 0; n < 4; ++n) {
            int j0 = w * 32 + n * 8 + tid4 * 2;
            float q0 = s_q[j0], q1 = s_q[j0 + 1];
            p0 += q0 * acc1[m][n][0] * acc2[m][n][0]
                + q1 * acc1[m][n][1] * acc2[m][n][1];
            p1 += q0 * acc1[m][n][2] * acc2[m][n][2]
                + q1 * acc1[m][n][3] * acc2[m][n][3];
        }
        p0 += __shfl_xor_sync(0xffffffffu, p0, 1);
        p0 += __shfl_xor_sync(0xffffffffu, p0, 2);
        p1 += __shfl_xor_sync(0xffffffffu, p1, 1);
        p1 += __shfl_xor_sync(0xffffffffu, p1, 2);
        if (tid4 == 0) {
            s_logits[w * 32 + m * 16 + g]     = p0 * (1.0f / 32.0f);
            s_logits[w * 32 + m * 16 + g + 8] = p1 * (1.0f / 32.0f);
        }
    }
    __syncwarp();

    // masked softmax: warp w = head, lane = neighbor k. att kept in register.
    float attv;
    {
        float mk = mask_attend[(size_t)bn * KK + lane];
        float l  = s_logits[w * 32 + lane];
        l = (mk > 0.f) ? l : -3.402823466e38f;
        float mx = l;
#pragma unroll
        for (int off = 16; off > 0; off >>= 1)
            mx = fmaxf(mx, __shfl_xor_sync(0xffffffffu, mx, off));
        float e = expf(l - mx);
        float s = e;
#pragma unroll
        for (int off = 16; off > 0; off >>= 1)
            s += __shfl_xor_sync(0xffffffffu, s, off);
        attv = mk * e / s;
    }

    // y[w][j] = sum_k att_k * EV[k][j]; lane owns 8 cols; EV direct from gmem.
    {
        const float4* gev = (const float4*)(h_EV + (size_t)bn * KK * 256);
        float4 y0 = make_float4(0.f, 0.f, 0.f, 0.f);
        float4 y1 = make_float4(0.f, 0.f, 0.f, 0.f);
#pragma unroll 4
        for (int k = 0; k < 32; ++k) {
            float a = __shfl_sync(0xffffffffu, attv, k);
            float4 e0 = gev[k * 64 + lane * 2];
            float4 e1 = gev[k * 64 + lane * 2 + 1];
            y0.x += a * e0.x; y0.y += a * e0.y; y0.z += a * e0.z; y0.w += a * e0.w;
            y1.x += a * e1.x; y1.y += a * e1.y; y1.z += a * e1.z; y1.w += a * e1.w;
        }
        uint4 u;
        u.x = h2u(__floats2half2_rn(y0.x, y0.y));
        u.y = h2u(__floats2half2_rn(y0.z, y0.w));
        u.z = h2u(__floats2half2_rn(y1.x, y1.y));
        u.w = h2u(__floats2half2_rn(y1.z, y1.w));
        ((uint4*)g_Y)[(size_t)bn * 128 + w * 32 + lane] = u;
    }
}

// ---------------- kernel2: out = LN(h_V + Y @ Mfull) ------------------------
// 125 blocks x 128 threads, 32 nodes/block, K=1024 fp16 mma.
__global__ void __launch_bounds__(128)
out_kernel(const float* __restrict__ h_V,
           const float* __restrict__ mask_V,
           const float* __restrict__ gain,
           const float* __restrict__ bias,
           float* __restrict__ out) {
    extern __shared__ float smf[];
    float*  sC   = smf;                        // 32 * 132 floats (padded)
    float*  s_mu = sC + 32 * 132;              // 32
    float*  s_iv = s_mu + 32;                  // 32 (mask/(sigma+eps))
    __half* sY   = (__half*)(s_iv + 32);       // 32 * 1032 halves

    const int t    = threadIdx.x;
    const int w    = t >> 5;
    const int lane = t & 31;
    const int g    = lane >> 2;
    const int tid4 = lane & 3;
    const int node0 = blockIdx.x * 32;

    // stage Y tile (64 KB)
    const uint4* gy4 = (const uint4*)g_Y;
#pragma unroll
    for (int it = 0; it < 32; ++it) {
        int f = it * 128 + t;                  // 0..4095
        int r = f >> 7, c = f & 127;
        *(uint4*)(sY + r * 1032 + c * 8) = gy4[(size_t)(node0 + r) * 128 + c];
    }
    __syncthreads();

    float acc[2][4][4];
#pragma unroll
    for (int m = 0; m < 2; ++m)
#pragma unroll
        for (int n = 0; n < 4; ++n)
#pragma unroll
            for (int c = 0; c < 4; ++c) acc[m][n][c] = 0.f;

    const int arow = lane & 15, acol8 = (lane >> 4) * 8;
    for (int ks = 0; ks < 64; ++ks) {
        unsigned int a[2][4];
#pragma unroll
        for (int m = 0; m < 2; ++m)
            ldsm_x4(a[m], sY + (m * 16 + arow) * 1032 + ks * 16 + acol8);
#pragma unroll
        for (int n = 0; n < 4; ++n) {
            uint2 b = g_Mf[(((w * 4 + n) * 64 + ks) * 32) + lane];
            mma16816(acc[0][n], a[0], b.x, b.y);
            mma16816(acc[1][n], a[1], b.x, b.y);
        }
    }

    // C -> smem (padded rows)
#pragma unroll
    for (int m = 0; m < 2; ++m)
#pragma unroll
        for (int n = 0; n < 4; ++n) {
            int col = w * 32 + n * 8 + tid4 * 2;
            int r0  = m * 16 + g;
            sC[r0 * 132 + col]       = acc[m][n][0];
            sC[r0 * 132 + col + 1]   = acc[m][n][1];
            sC[(r0 + 8) * 132 + col]     = acc[m][n][2];
            sC[(r0 + 8) * 132 + col + 1] = acc[m][n][3];
        }
    __syncthreads();

    // residual + LN stats: thread (r = t>>2, q = t&3) covers 32 cols of row r
    {
        int r = t >> 2, q = t & 3;
        int node = node0 + r;
        const float4* hv4 = (const float4*)h_V;
        float sum = 0.f, sq = 0.f;
#pragma unroll
        for (int i = 0; i < 8; ++i) {
            int c4 = q * 8 + i;
            float4 cv = *(float4*)&sC[r * 132 + c4 * 4];
            float4 hv = hv4[(size_t)node * 32 + c4];
            cv.x += hv.x; cv.y += hv.y; cv.z += hv.z; cv.w += hv.w;
            *(float4*)&sC[r * 132 + c4 * 4] = cv;
            sum += cv.x + cv.y + cv.z + cv.w;
            sq  += cv.x * cv.x + cv.y * cv.y + cv.z * cv.z + cv.w * cv.w;
        }
        sum += __shfl_xor_sync(0xffffffffu, sum, 1);
        sum += __shfl_xor_sync(0xffffffffu, sum, 2);
        sq  += __shfl_xor_sync(0xffffffffu, sq, 1);
        sq  += __shfl_xor_sync(0xffffffffu, sq, 2);
        if (q == 0) {
            float mu  = sum * (1.f / 128.f);
            float var = (sq - sum * mu) * (1.f / 127.f);
            float sig = sqrtf(var + EPSC);
            s_mu[r] = mu;
            s_iv[r] = mask_V[node] / (sig + EPSC);
        }
    }
    __syncthreads();

    // write out: o = mask*(gain*(x-mu)/(sig+eps) + bias)
    const float4* g4 = (const float4*)gain;
    const float4* b4 = (const float4*)bias;
    float4* o4 = (float4*)out;
#pragma unroll
    for (int it = 0; it < 8; ++it) {
        int f4 = it * 128 + t;                 // 0..1023
        int r  = f4 >> 5, c4 = f4 & 31;
        float mu = s_mu[r], iv = s_iv[r];
        float mk = (iv != 0.f || true) ? 1.f : 1.f; // mask folded into iv; bias needs raw mask
        float mraw = mask_V[node0 + r];
        float4 x = *(float4*)&sC[r * 132 + c4 * 4];
        float4 gg = g4[c4], bb = b4[c4];
        float4 o;
        o.x = (x.x - mu) * iv * gg.x + mraw * bb.x;
        o.y = (x.y - mu) * iv * gg.y + mraw * bb.y;
        o.z = (x.z - mu) * iv * gg.z + mraw * bb.z;
        o.w = (x.w - mu) * iv * gg.w + mraw * bb.w;
        (void)mk;
        o4[(size_t)(node0 + r) * 32 + c4] = o;
    }
}

static const int ATTN_SMEM = (128 + 128) * 4 + 2 * 32 * KROW * 2;
static const int OUT_SMEM  = (32 * 132 + 64) * 4 + 32 * 1032 * 2;

extern "C" void kernel_launch(void* const* d_in, const int* in_sizes, int n_in,
                              void* d_out, int out_size) {
    const float* h_V         = (const float*)d_in[0];
    const float* h_EV        = (const float*)d_in[1];
    const float* h_KV        = (const float*)d_in[2];
    const float* h_KE        = (const float*)d_in[3];
    const float* mask_V      = (const float*)d_in[4];
    const float* mask_attend = (const float*)d_in[5];
    const float* W_Q         = (const float*)d_in[6];
    const float* W_K1        = (const float*)d_in[7];
    const float* W_K2        = (const float*)d_in[8];
    const float* W_V         = (const float*)d_in[9];
    const float* W_O         = (const float*)d_in[10];
    const float* gain        = (const float*)d_in[11];
    const float* bias        = (const float*)d_in[12];
    float* out = (float*)d_out;

    pack_kernel<<<48, 256>>>(W_Q, W_K1, W_K2, W_V, W_O);
    qgemm_kernel<<<125, 128>>>(h_V);

    cudaFuncSetAttribute(attn_kernel,
                         cudaFuncAttributeMaxDynamicSharedMemorySize, ATTN_SMEM);
    attn_kernel<<<BB * NN, 128, ATTN_SMEM>>>(h_EV, h_KV, h_KE, mask_attend);

    cudaFuncSetAttribute(out_kernel,
                         cudaFuncAttributeMaxDynamicSharedMemorySize, OUT_SMEM);
    out_kernel<<<125, 128, OUT_SMEM>>>(h_V, mask_V, gain, bias, out);
}

// round 5
// speedup vs baseline: 4.1654x; 1.1363x over previous
#include <cuda_runtime.h>
#include <cuda_fp16.h>
#include <cstdint>
#include <math.h>

#define BB   2
#define NN   2000
#define KK   32
#define HH   128
#define EPSC 1e-6f

// ---------------- device scratch (__device__ globals, no alloc) -------------
__device__ uint2 g_WQf[16 * 8 * 32];
__device__ uint2 g_W1f[16 * 8 * 32];
__device__ uint2 g_W2f[16 * 8 * 32];
// Fused value matrix Mfull[1024 x 128] fp16 fragments (Mfull = W_V(head) x W_O)
__device__ uint2 g_Mf[16 * 64 * 32];
__device__ __half g_Qh[4000 * 128];
__device__ __half g_Y [4000 * 1024];

__device__ __forceinline__ unsigned int h2u(__half2 h) {
    return *(unsigned int*)&h;
}
__device__ __forceinline__ void cp_async16(void* dst_smem, const void* src) {
    unsigned int d = (unsigned int)__cvta_generic_to_shared(dst_smem);
    asm volatile("cp.async.cg.shared.global [%0], [%1], 16;" :: "r"(d), "l"(src));
}
__device__ __forceinline__ void cp_async_commit() {
    asm volatile("cp.async.commit_group;");
}
__device__ __forceinline__ void cp_async_wait0() {
    asm volatile("cp.async.wait_group 0;");
}

// ---------------- pack: weight fragments + Mfull ----------------------------
__global__ void pack_kernel(const float* __restrict__ WQ,
                            const float* __restrict__ WK1,
                            const float* __restrict__ WK2,
                            const float* __restrict__ WV,
                            const float* __restrict__ WO) {
    __shared__ float sWO[128 * 33];
    __shared__ float sWV[32 * 32];
    if (blockIdx.x < 16) {
        int t = blockIdx.x * 256 + threadIdx.x;   // 0..4095
        int lane = t & 31;
        int ks   = (t >> 5) & 7;
        int nt8  = t >> 8;
        int g    = lane >> 2;
        int tid4 = lane & 3;
        int n    = nt8 * 8 + g;
        int k0   = ks * 16 + tid4 * 2;
        uint2 uq, u1, u2;
        uq.x = h2u(__floats2half2_rn(WQ [n * 128 + k0],     WQ [n * 128 + k0 + 1]));
        uq.y = h2u(__floats2half2_rn(WQ [n * 128 + k0 + 8], WQ [n * 128 + k0 + 9]));
        u1.x = h2u(__floats2half2_rn(WK1[n * 128 + k0],     WK1[n * 128 + k0 + 1]));
        u1.y = h2u(__floats2half2_rn(WK1[n * 128 + k0 + 8], WK1[n * 128 + k0 + 9]));
        u2.x = h2u(__floats2half2_rn(WK2[n * 128 + k0],     WK2[n * 128 + k0 + 1]));
        u2.y = h2u(__floats2half2_rn(WK2[n * 128 + k0 + 8], WK2[n * 128 + k0 + 9]));
        g_WQf[t] = uq; g_W1f[t] = u1; g_W2f[t] = u2;
    } else {
        int bid = blockIdx.x - 16;        // 0..31
        int h   = bid >> 3;               // head
        int jc  = bid & 7;                // 32-wide j chunk within head
        int tid = threadIdx.x;
        for (int i = tid; i < 128 * 32; i += 256) {
            int o = i >> 5, ii = i & 31;
            sWO[o * 33 + ii] = WO[o * 128 + h * 32 + ii];
        }
        for (int i = tid; i < 32 * 32; i += 256) {
            int ii = i >> 5, jj = i & 31;
            sWV[ii * 32 + jj] = WV[(h * 32 + ii) * 256 + jc * 32 + jj];
        }
        __syncthreads();
        int o    = tid & 127;
        int jsel = tid >> 7;
        float wo[32];
#pragma unroll
        for (int ii = 0; ii < 32; ++ii) wo[ii] = sWO[o * 33 + ii];
        float m[16];
#pragma unroll
        for (int jj2 = 0; jj2 < 16; ++jj2) {
            int jj = jsel * 16 + jj2;
            float a = 0.f;
#pragma unroll
            for (int ii = 0; ii < 32; ++ii) a += sWV[ii * 32 + jj] * wo[ii];
            m[jj2] = a;
        }
        int ks = h * 16 + jc * 2 + jsel;
        int nt = o >> 3;
        int g  = o & 7;
#pragma unroll
        for (int tid4 = 0; tid4 < 4; ++tid4) {
            int k0l = tid4 * 2;
            uint2 u;
            u.x = h2u(__floats2half2_rn(m[k0l],     m[k0l + 1]));
            u.y = h2u(__floats2half2_rn(m[k0l + 8], m[k0l + 9]));
            g_Mf[(nt * 64 + ks) * 32 + (g << 2 | tid4)] = u;
        }
    }
}

// ---------------- PTX helpers ----------------
__device__ __forceinline__ void ldsm_x4(unsigned int* r, const void* p) {
    unsigned int a = (unsigned int)__cvta_generic_to_shared(p);
    asm volatile("ldmatrix.sync.aligned.m8n8.x4.shared.b16 {%0,%1,%2,%3}, [%4];"
                 : "=r"(r[0]), "=r"(r[1]), "=r"(r[2]), "=r"(r[3]) : "r"(a));
}
__device__ __forceinline__ void mma16816(float* d, const unsigned int* a,
                                         unsigned int b0, unsigned int b1) {
    asm volatile("mma.sync.aligned.m16n8k16.row.col.f32.f16.f16.f32 "
                 "{%0,%1,%2,%3}, {%4,%5,%6,%7}, {%8,%9}, {%0,%1,%2,%3};"
                 : "+f"(d[0]), "+f"(d[1]), "+f"(d[2]), "+f"(d[3])
                 : "r"(a[0]), "r"(a[1]), "r"(a[2]), "r"(a[3]), "r"(b0), "r"(b1));
}

// ---------------- qgemm: Q = h_V @ W_Q^T -> g_Qh (fp16 mma) -----------------
__global__ void __launch_bounds__(128)
qgemm_kernel(const float* __restrict__ h_V) {
    __shared__ __half sA[32 * 136];
    const int t    = threadIdx.x;
    const int w    = t >> 5;
    const int lane = t & 31;
    const int g    = lane >> 2;
    const int tid4 = lane & 3;
    const int node0 = blockIdx.x * 32;

    const float4* hv4 = (const float4*)h_V;
#pragma unroll
    for (int it = 0; it < 8; ++it) {
        int f4 = it * 128 + t;
        int r  = f4 >> 5, c4 = f4 & 31;
        float4 v = hv4[(size_t)(node0 + r) * 32 + c4];
        __half2* p = (__half2*)(sA + r * 136 + c4 * 4);
        p[0] = __floats2half2_rn(v.x, v.y);
        p[1] = __floats2half2_rn(v.z, v.w);
    }
    __syncthreads();

    float acc[2][4][4];
#pragma unroll
    for (int m = 0; m < 2; ++m)
#pragma unroll
        for (int n = 0; n < 4; ++n)
#pragma unroll
            for (int c = 0; c < 4; ++c) acc[m][n][c] = 0.f;

    const int arow = lane & 15, acol8 = (lane >> 4) * 8;
#pragma unroll
    for (int ks = 0; ks < 8; ++ks) {
        unsigned int a[2][4];
#pragma unroll
        for (int m = 0; m < 2; ++m)
            ldsm_x4(a[m], sA + (m * 16 + arow) * 136 + ks * 16 + acol8);
#pragma unroll
        for (int n = 0; n < 4; ++n) {
            uint2 b = g_WQf[(((w * 4 + n) * 8 + ks) * 32) + lane];
            mma16816(acc[0][n], a[0], b.x, b.y);
            mma16816(acc[1][n], a[1], b.x, b.y);
        }
    }
#pragma unroll
    for (int m = 0; m < 2; ++m)
#pragma unroll
        for (int n = 0; n < 4; ++n) {
            int col = w * 32 + n * 8 + tid4 * 2;
            int r0  = node0 + m * 16 + g;
            *(__half2*)&g_Qh[(size_t)r0 * 128 + col] =
                __floats2half2_rn(acc[m][n][0], acc[m][n][1]);
            *(__half2*)&g_Qh[(size_t)(r0 + 8) * 128 + col] =
                __floats2half2_rn(acc[m][n][2], acc[m][n][3]);
        }
}

// ---------------- attn: per node -> Y ---------------------------------------
#define KROW 136
__global__ void __launch_bounds__(128, 4)
attn_kernel(const float* __restrict__ h_EV,
            const float* __restrict__ h_KV,
            const float* __restrict__ h_KE,
            const float* __restrict__ mask_attend) {
    extern __shared__ float smbuf[];
    float*  s_q      = smbuf;                    // 128
    float*  s_logits = s_q + 128;                // 128
    float*  s_ev     = s_logits + 128;           // 32*256 = 8192
    __half* s_keh    = (__half*)(s_ev + 8192);   // 32*KROW
    __half* s_kvh    = s_keh + 32 * KROW;        // 32*KROW

    const int bn   = blockIdx.x;
    const int t    = threadIdx.x;
    const int w    = t >> 5;
    const int lane = t & 31;
    const int g    = lane >> 2;
    const int tid4 = lane & 3;

    // prefetch EV (fp32, consumed as fp32) via cp.async — overlaps mma phase
    {
        const float4* gev = (const float4*)(h_EV + (size_t)bn * KK * 256);
#pragma unroll
        for (int it = 0; it < 16; ++it) {
            int idx = it * 128 + t;              // 0..2047 float4s
            cp_async16(s_ev + idx * 4, gev + idx);
        }
        cp_async_commit();
    }

    // stage KE/KV as fp16
    {
        const float4* gke = (const float4*)(h_KE + (size_t)bn * KK * 128);
        const float4* gkv = (const float4*)(h_KV + (size_t)bn * KK * 128);
#pragma unroll
        for (int r = 0; r < 8; ++r) {
            int e4 = r * 128 + t;
            int k  = e4 >> 5;
            int j  = (e4 & 31) * 4;
            float4 a = gke[e4];
            float4 b = gkv[e4];
            uint2 ua, ub;
            ua.x = h2u(__floats2half2_rn(a.x, a.y));
            ua.y = h2u(__floats2half2_rn(a.z, a.w));
            ub.x = h2u(__floats2half2_rn(b.x, b.y));
            ub.y = h2u(__floats2half2_rn(b.z, b.w));
            *(uint2*)(s_keh + k * KROW + j) = ua;
            *(uint2*)(s_kvh + k * KROW + j) = ub;
        }
        s_q[t] = __half2float(g_Qh[(size_t)bn * 128 + t]);
    }
    __syncthreads();

    // K1/K2 mma (fp16 in, fp32 acc)
    float acc1[2][4][4], acc2[2][4][4];
#pragma unroll
    for (int m = 0; m < 2; ++m)
#pragma unroll
        for (int n = 0; n < 4; ++n)
#pragma unroll
            for (int c = 0; c < 4; ++c) { acc1[m][n][c] = 0.f; acc2[m][n][c] = 0.f; }

    const int arow = lane & 15, acol8 = (lane >> 4) * 8;
#pragma unroll
    for (int ks = 0; ks < 8; ++ks) {
        unsigned int a1[2][4], a2[2][4];
#pragma unroll
        for (int m = 0; m < 2; ++m) {
            ldsm_x4(a1[m], s_keh + (m * 16 + arow) * KROW + ks * 16 + acol8);
            ldsm_x4(a2[m], s_kvh + (m * 16 + arow) * KROW + ks * 16 + acol8);
        }
#pragma unroll
        for (int n = 0; n < 4; ++n) {
            int f = (((w * 4 + n) * 8 + ks) * 32) + lane;
            uint2 b1 = g_W1f[f];
            uint2 b2 = g_W2f[f];
            mma16816(acc1[0][n], a1[0], b1.x, b1.y);
            mma16816(acc1[1][n], a1[1], b1.x, b1.y);
            mma16816(acc2[0][n], a2[0], b2.x, b2.y);
            mma16816(acc2[1][n], a2[1], b2.x, b2.y);
        }
    }

    // logits[h=w][k] = (1/32) sum_i q*K1*K2
#pragma unroll
    for (int m = 0; m < 2; ++m) {
        float p0 = 0.f, p1 = 0.f;
#pragma unroll
        for (int n = 0; n < 4; ++n) {
            int j0 = w * 32 + n * 8 + tid4 * 2;
            float q0 = s_q[j0], q1 = s_q[j0 + 1];
            p0 += q0 * acc1[m][n][0] * acc2[m][n][0]
                + q1 * acc1[m][n][1] * acc2[m][n][1];
            p1 += q0 * acc1[m][n][2] * acc2[m][n][2]
                + q1 * acc1[m][n][3] * acc2[m][n][3];
        }
        p0 += __shfl_xor_sync(0xffffffffu, p0, 1);
        p0 += __shfl_xor_sync(0xffffffffu, p0, 2);
        p1 += __shfl_xor_sync(0xffffffffu, p1, 1);
        p1 += __shfl_xor_sync(0xffffffffu, p1, 2);
        if (tid4 == 0) {
            s_logits[w * 32 + m * 16 + g]     = p0 * (1.0f / 32.0f);
            s_logits[w * 32 + m * 16 + g + 8] = p1 * (1.0f / 32.0f);
        }
    }
    __syncwarp();

    // masked softmax: warp w = head, lane = neighbor k
    float attv;
    {
        float mk = mask_attend[(size_t)bn * KK + lane];
        float l  = s_logits[w * 32 + lane];
        l = (mk > 0.f) ? l : -3.402823466e38f;
        float mx = l;
#pragma unroll
        for (int off = 16; off > 0; off >>= 1)
            mx = fmaxf(mx, __shfl_xor_sync(0xffffffffu, mx, off));
        float e = expf(l - mx);
        float s = e;
#pragma unroll
        for (int off = 16; off > 0; off >>= 1)
            s += __shfl_xor_sync(0xffffffffu, s, off);
        attv = mk * e / s;
    }

    cp_async_wait0();
    __syncthreads();

    // y[w][j] = sum_k att_k * EV[k][j]; lane owns cols lane*4..+4 and 128+lane*4..+4
    {
        float4 y0 = make_float4(0.f, 0.f, 0.f, 0.f);
        float4 y1 = make_float4(0.f, 0.f, 0.f, 0.f);
#pragma unroll 4
        for (int k = 0; k < 32; ++k) {
            float a = __shfl_sync(0xffffffffu, attv, k);
            float4 e0 = *(const float4*)(s_ev + k * 256 + lane * 4);
            float4 e1 = *(const float4*)(s_ev + k * 256 + 128 + lane * 4);
            y0.x += a * e0.x; y0.y += a * e0.y; y0.z += a * e0.z; y0.w += a * e0.w;
            y1.x += a * e1.x; y1.y += a * e1.y; y1.z += a * e1.z; y1.w += a * e1.w;
        }
        uint2 u0, u1;
        u0.x = h2u(__floats2half2_rn(y0.x, y0.y));
        u0.y = h2u(__floats2half2_rn(y0.z, y0.w));
        u1.x = h2u(__floats2half2_rn(y1.x, y1.y));
        u1.y = h2u(__floats2half2_rn(y1.z, y1.w));
        ((uint2*)g_Y)[(size_t)bn * 256 + w * 64 + lane]      = u0;
        ((uint2*)g_Y)[(size_t)bn * 256 + w * 64 + 32 + lane] = u1;
    }
}

// ---------------- out: out = LN(h_V + Y @ Mfull) ----------------------------
// 250 blocks x 256 threads; 16 nodes/block; 8 warps: n-tile = w&3, k-half = w>>2.
__global__ void __launch_bounds__(256)
out_kernel(const float* __restrict__ h_V,
           const float* __restrict__ mask_V,
           const float* __restrict__ gain,
           const float* __restrict__ bias,
           float* __restrict__ out) {
    extern __shared__ float smf[];
    float*  sRed = smf;                        // 2 * 16 * 132
    float*  s_mu = sRed + 2 * 16 * 132;        // 16
    float*  s_iv = s_mu + 16;                  // 16
    float*  s_mk = s_iv + 16;                  // 16
    __half* sY   = (__half*)(s_mk + 16);       // 16 * 1032

    const int t    = threadIdx.x;
    const int w    = t >> 5;
    const int lane = t & 31;
    const int g    = lane >> 2;
    const int tid4 = lane & 3;
    const int node0 = blockIdx.x * 16;
    const int nt4  = w & 3;                    // 32-col tile
    const int kh   = w >> 2;                   // K half

    // stage Y tile (33 KB) via cp.async
    {
#pragma unroll
        for (int it = 0; it < 8; ++it) {
            int f = it * 256 + t;              // 0..2047 (16B chunks)
            int r = f >> 7, c = f & 127;
            cp_async16(sY + r * 1032 + c * 8,
                       g_Y + (size_t)(node0 + r) * 1024 + c * 8);
        }
        cp_async_commit();
        cp_async_wait0();
    }
    __syncthreads();

    float acc[4][4];
#pragma unroll
    for (int n = 0; n < 4; ++n)
#pragma unroll
        for (int c = 0; c < 4; ++c) acc[n][c] = 0.f;

    const int arow = lane & 15, acol8 = (lane >> 4) * 8;
#pragma unroll 2
    for (int ksl = 0; ksl < 32; ++ksl) {
        int ks = kh * 32 + ksl;
        unsigned int a[4];
        ldsm_x4(a, sY + arow * 1032 + ks * 16 + acol8);
#pragma unroll
        for (int n = 0; n < 4; ++n) {
            uint2 b = g_Mf[(((nt4 * 4 + n) * 64 + ks) * 32) + lane];
            mma16816(acc[n], a, b.x, b.y);
        }
    }

    // partial C -> smem
#pragma unroll
    for (int n = 0; n < 4; ++n) {
        int col = (nt4 * 4 + n) * 8 + tid4 * 2;
        float* base = sRed + kh * 16 * 132;
        base[g * 132 + col]           = acc[n][0];
        base[g * 132 + col + 1]       = acc[n][1];
        base[(g + 8) * 132 + col]     = acc[n][2];
        base[(g + 8) * 132 + col + 1] = acc[n][3];
    }
    __syncthreads();

    // reduce K-halves + residual + LN stats: r = t>>4 (row), q = t&15 (8 cols)
    {
        int r = t >> 4, q = t & 15;
        int node = node0 + r;
        const float4* hv4 = (const float4*)h_V;
        float sum = 0.f, sq = 0.f;
#pragma unroll
        for (int i = 0; i < 2; ++i) {
            int c4 = q * 2 + i;
            float4 c0 = *(float4*)&sRed[r * 132 + c4 * 4];
            float4 c1 = *(float4*)&sRed[16 * 132 + r * 132 + c4 * 4];
            float4 hv = hv4[(size_t)node * 32 + c4];
            float4 x;
            x.x = c0.x + c1.x + hv.x;
            x.y = c0.y + c1.y + hv.y;
            x.z = c0.z + c1.z + hv.z;
            x.w = c0.w + c1.w + hv.w;
            *(float4*)&sRed[r * 132 + c4 * 4] = x;
            sum += x.x + x.y + x.z + x.w;
            sq  += x.x * x.x + x.y * x.y + x.z * x.z + x.w * x.w;
        }
#pragma unroll
        for (int off = 8; off > 0; off >>= 1) {
            sum += __shfl_xor_sync(0xffffffffu, sum, off, 16);
            sq  += __shfl_xor_sync(0xffffffffu, sq, off, 16);
        }
        if (q == 0) {
            float mu  = sum * (1.f / 128.f);
            float var = (sq - sum * mu) * (1.f / 127.f);
            float sig = sqrtf(var + EPSC);
            float mk  = mask_V[node];
            s_mu[r] = mu;
            s_iv[r] = mk / (sig + EPSC);
            s_mk[r] = mk;
        }
    }
    __syncthreads();

    // write out
    const float4* g4 = (const float4*)gain;
    const float4* b4 = (const float4*)bias;
    float4* o4 = (float4*)out;
#pragma unroll
    for (int it = 0; it < 2; ++it) {
        int f4 = it * 256 + t;                 // 0..511
        int r  = f4 >> 5, c4 = f4 & 31;
        float mu = s_mu[r], iv = s_iv[r], mk = s_mk[r];
        float4 x = *(float4*)&sRed[r * 132 + c4 * 4];
        float4 gg = g4[c4], bb = b4[c4];
        float4 o;
        o.x = (x.x - mu) * iv * gg.x + mk * bb.x;
        o.y = (x.y - mu) * iv * gg.y + mk * bb.y;
        o.z = (x.z - mu) * iv * gg.z + mk * bb.z;
        o.w = (x.w - mu) * iv * gg.w + mk * bb.w;
        o4[(size_t)(node0 + r) * 32 + c4] = o;
    }
}

static const int ATTN_SMEM = (128 + 128 + 8192) * 4 + 2 * 32 * KROW * 2;
static const int OUT_SMEM  = (2 * 16 * 132 + 48) * 4 + 16 * 1032 * 2;

extern "C" void kernel_launch(void* const* d_in, const int* in_sizes, int n_in,
                              void* d_out, int out_size) {
    const float* h_V         = (const float*)d_in[0];
    const float* h_EV        = (const float*)d_in[1];
    const float* h_KV        = (const float*)d_in[2];
    const float* h_KE        = (const float*)d_in[3];
    const float* mask_V      = (const float*)d_in[4];
    const float* mask_attend = (const float*)d_in[5];
    const float* W_Q         = (const float*)d_in[6];
    const float* W_K1        = (const float*)d_in[7];
    const float* W_K2        = (const float*)d_in[8];
    const float* W_V         = (const float*)d_in[9];
    const float* W_O         = (const float*)d_in[10];
    const float* gain        = (const float*)d_in[11];
    const float* bias        = (const float*)d_in[12];
    float* out = (float*)d_out;

    pack_kernel<<<48, 256>>>(W_Q, W_K1, W_K2, W_V, W_O);
    qgemm_kernel<<<125, 128>>>(h_V);

    cudaFuncSetAttribute(attn_kernel,
                         cudaFuncAttributeMaxDynamicSharedMemorySize, ATTN_SMEM);
    attn_kernel<<<BB * NN, 128, ATTN_SMEM>>>(h_EV, h_KV, h_KE, mask_attend);

    cudaFuncSetAttribute(out_kernel,
                         cudaFuncAttributeMaxDynamicSharedMemorySize, OUT_SMEM);
    out_kernel<<<250, 256, OUT_SMEM>>>(h_V, mask_V, gain, bias, out);
}